// round 8
// baseline (speedup 1.0000x reference)
#include <cuda_runtime.h>

// InnerProduct: ip[r,p] = sum_f w[p,f]^2 * sum_e x[r,f,e]^2
// x: [32768, 64, 128] f32, w: [10, 64] f32, out: [32768, 10] f32
//
// DRAM-bound (1 GiB single-pass read of x) at ~92% of HBM spec (measured
// plateau). R7 structure (one-shot CTA/row, 8 warps x 8 fields, 8 front-
// batched streaming LDG.128/thread, 9-SHFL fold-reduce) with a SPLIT barrier:
// producer-only warps 5..7 bar.arrive and retire immediately after their
// xsq store; consumer warps 0..4 bar.sync on the same 256-thread count.

#define BATCH    32768
#define N_FIELDS 64
#define EMBED    128
#define OUT_SZ   10
#define THREADS  256

__global__ __launch_bounds__(THREADS)
void innerproduct_kernel(const float* __restrict__ x,
                         const float* __restrict__ w,
                         float* __restrict__ out)
{
    const int r    = blockIdx.x;
    const int tid  = threadIdx.x;
    const int warp = tid >> 5;
    const int lane = tid & 31;

    __shared__ float xsq[N_FIELDS];

    // Warp owns fields warp*8 .. warp*8+7 (contiguous 4KB of the row);
    // lane l takes float4 #l of each field. 8 independent LDG.128, streaming.
    const float4* __restrict__ xr =
        reinterpret_cast<const float4*>(x)
        + (size_t)r * (N_FIELDS * EMBED / 4) + warp * 8 * (EMBED / 4) + lane;

    float4 vv[8];
#pragma unroll
    for (int i = 0; i < 8; i++)
        vv[i] = __ldcs(&xr[i * (EMBED / 4)]);

    // Weight loads (reused by every CTA -> default caching) issue now so
    // their latency hides under the x-load wait.
    const int p = tid >> 4;   // output 0..9 for tid < 160
    const int g = tid & 15;   // owns fields g*4..g*4+3
    float wsq[4] = {0.f, 0.f, 0.f, 0.f};
    if (tid < OUT_SZ * 16) {
#pragma unroll
        for (int k = 0; k < 4; k++) {
            float wv = __ldg(&w[p * N_FIELDS + g * 4 + k]);
            wsq[k] = wv * wv;
        }
    }

    float v[8];
#pragma unroll
    for (int i = 0; i < 8; i++)
        v[i] = vv[i].x * vv[i].x + vv[i].y * vv[i].y
             + vv[i].z * vv[i].z + vv[i].w * vv[i].w;

    // Fold-and-split multi-value warp reduce: 8 -> 1 per lane in 9 SHFLs.
    // Afterward lane l holds the full sum of field warp*8 + ((l>>2)&7).
    {
        const bool hi16 = (lane & 16) != 0;
#pragma unroll
        for (int j = 0; j < 4; j++) {
            float send = hi16 ? v[j] : v[j + 4];
            float recv = __shfl_xor_sync(0xffffffffu, send, 16);
            v[j] = (hi16 ? v[j + 4] : v[j]) + recv;
        }
        const bool hi8 = (lane & 8) != 0;
#pragma unroll
        for (int j = 0; j < 2; j++) {
            float send = hi8 ? v[j] : v[j + 2];
            float recv = __shfl_xor_sync(0xffffffffu, send, 8);
            v[j] = (hi8 ? v[j + 2] : v[j]) + recv;
        }
        const bool hi4 = (lane & 4) != 0;
        {
            float send = hi4 ? v[0] : v[1];
            float recv = __shfl_xor_sync(0xffffffffu, send, 4);
            v[0] = (hi4 ? v[1] : v[0]) + recv;
        }
        v[0] += __shfl_xor_sync(0xffffffffu, v[0], 2);
        v[0] += __shfl_xor_sync(0xffffffffu, v[0], 1);
    }
    if ((lane & 3) == 0)
        xsq[warp * 8 + ((lane >> 2) & 7)] = v[0];

    // Split barrier: producer-only warps arrive (non-blocking) and retire;
    // consumer warps 0..4 block until all 256 threads have arrived.
    // bar.arrive/bar.sync on barrier 0 drain pending STS (HW-native fence).
    if (warp >= 5) {
        asm volatile("bar.arrive 0, %0;" :: "r"(THREADS) : "memory");
        return;
    }
    asm volatile("bar.sync 0, %0;" :: "r"(THREADS) : "memory");

    // Tail: 10 outputs x 16 threads (warps 0..4).
    if (tid < OUT_SZ * 16) {
        float s = 0.f;
#pragma unroll
        for (int k = 0; k < 4; k++)
            s = fmaf(xsq[g * 4 + k], wsq[k], s);
#pragma unroll
        for (int sh = 8; sh >= 1; sh >>= 1)
            s += __shfl_xor_sync(0xffffffffu, s, sh);
        if (g == 0)
            __stcs(&out[r * OUT_SZ + p], s);
    }
}

extern "C" void kernel_launch(void* const* d_in, const int* in_sizes, int n_in,
                              void* d_out, int out_size)
{
    const float* x = (const float*)d_in[0];
    const float* w = (const float*)d_in[1];
    float* out = (float*)d_out;

    innerproduct_kernel<<<BATCH, THREADS>>>(x, w, out);
}